// round 12
// baseline (speedup 1.0000x reference)
#include <cuda_runtime.h>
#include <cuda_fp16.h>
#include <cstdint>

#define NQ      8
#define DIM     256
#define MT      64               // batch rows per CTA
#define NCHUNK  4                // N processed in 4 chunks of 128 cols
#define CSLICES 8                // B slices per chunk: 4 Whi (dual pass) + 4 Wlo (single)
#define GSLICES 32               // total B slices
#define BSTRIDE 144              // B smem row: 128 B data + 16 B pad
#define BROWS   128              // n-rows per slice
#define BSLICE  (BROWS * BSTRIDE)   // 18432 B per slice
#define ASTRIDE 1040             // A smem row: 1024 B data + 16 B pad
#define ABYTES  (MT * ASTRIDE)   // 66560
#define ZBYTES  (4 * 64 * 8 * 4) // 8192: zacc[wn][row][8] fp32
#define SMEM_TOTAL (ABYTES + 2 * BSLICE + 64 + ZBYTES)   // 111680 (2 CTAs/SM)

// W slice images, laid out exactly as the smem B buffer (padded [n][k] rows).
// Slice gs = chunk*8 + s:  s 0-3 = Whi j-block s,  s 4-7 = Wlo j-block s-4.
__device__ __align__(128) unsigned char d_B[GSLICES * BSLICE];  // 589824 B

// ---------------- helpers ----------------
__device__ __forceinline__ uint32_t smem_u32(const void* p) {
    uint32_t a;
    asm("{ .reg .u64 t; cvta.to.shared.u64 t, %1; cvt.u32.u64 %0, t; }" : "=r"(a) : "l"(p));
    return a;
}

#define MBAR_INIT(a, n)  asm volatile("mbarrier.init.shared.b64 [%0], %1;" :: "r"(a), "r"((uint32_t)(n)) : "memory")
#define MBAR_EXPECT(a, n) asm volatile("mbarrier.arrive.expect_tx.shared.b64 _, [%0], %1;" :: "r"(a), "r"((uint32_t)(n)) : "memory")
#define MBAR_WAIT(a, ph) do {                                                        \
    uint32_t _m = (a), _p = (ph), _d;                                                \
    asm volatile("{ .reg .pred p; mbarrier.try_wait.parity.acquire.cta.shared::cta.b64 p, [%1], %2; selp.b32 %0,1,0,p; }" \
                 : "=r"(_d) : "r"(_m), "r"(_p) : "memory");                          \
    if (!_d) {                                                                       \
        asm volatile("{ .reg .pred P1; W%=: mbarrier.try_wait.parity.acquire.cta.shared::cta.b64 P1, [%0], %1, 0x989680;" \
                     " @P1 bra.uni D%=; bra.uni W%=; D%=: }" :: "r"(_m), "r"(_p) : "memory"); \
    }                                                                                \
} while (0)

__device__ __forceinline__ void bulk_g2s(uint32_t dst, const void* src, uint32_t bytes, uint32_t mbar) {
    asm volatile("cp.async.bulk.shared::cluster.global.mbarrier::complete_tx::bytes [%0], [%1], %2, [%3];"
        :: "r"(dst), "l"(src), "r"(bytes), "r"(mbar) : "memory");
}

#define LDSM4(r, addr) \
    asm volatile("ldmatrix.sync.aligned.m8n8.x4.shared.b16 {%0,%1,%2,%3}, [%4];" \
        : "=r"((r)[0]), "=r"((r)[1]), "=r"((r)[2]), "=r"((r)[3]) : "r"(addr))

#define MMA16816(c, a, bb0, bb1) \
    asm volatile("mma.sync.aligned.m16n8k16.row.col.f32.f16.f16.f32 " \
        "{%0,%1,%2,%3}, {%4,%5,%6,%7}, {%8,%9}, {%0,%1,%2,%3};" \
        : "+f"((c)[0]), "+f"((c)[1]), "+f"((c)[2]), "+f"((c)[3]) \
        : "r"((a)[0]), "r"((a)[1]), "r"((a)[2]), "r"((a)[3]), "r"(bb0), "r"(bb1))

// complex fused mul-add into (dr, di)
#define CMADD(dr, di, ur, ui, ar, ai) \
    { dr += (ur) * (ar) - (ui) * (ai); di += (ur) * (ai) + (ui) * (ar); }

// ============================================================
// Kernel A: build U column j (one warp per column, shuffle-based),
// then emit fp16 Whi + Wlo slice images.  32 blocks x 256 threads.
// State: index idx = lane*8 + local  (lane = bits 7..3, local = bits 2..0)
// ============================================================
__global__ void build_U_kernel(const float* __restrict__ w) {
    __shared__ float um[48][8];   // per gate: u00r,u00i,u01r,u01i,u10r,u10i,u11r,u11i
    const int tid = threadIdx.x;

    if (tid < 48) {
        const float phi = w[tid * 3 + 0];
        const float th  = w[tid * 3 + 1];
        const float om  = w[tid * 3 + 2];
        float sth, ct;  sincosf(0.5f * th, &sth, &ct);
        float sa, ca;   sincosf(0.5f * (phi + om), &sa, &ca);
        float sb, cb;   sincosf(0.5f * (phi - om), &sb, &cb);
        um[tid][0] =  ca * ct;  um[tid][1] = -sa * ct;    // u00
        um[tid][2] = -cb * sth; um[tid][3] = -sb * sth;   // u01
        um[tid][4] =  cb * sth; um[tid][5] = -sb * sth;   // u10
        um[tid][6] =  ca * ct;  um[tid][7] =  sa * ct;    // u11
    }
    __syncthreads();

    const int warp = tid >> 5, lane = tid & 31;
    const int j = blockIdx.x * 8 + warp;   // column 0..255

    float sr[8], si[8];
#pragma unroll
    for (int i = 0; i < 8; ++i) {
        sr[i] = (lane * 8 + i == j) ? 1.f : 0.f;
        si[i] = 0.f;
    }

    for (int l = 0; l < 6; ++l) {
        const int r = l % 7 + 1;

        // ---- Rot gates (commute across wires) ----
        for (int q = 0; q < 8; ++q) {
            const float* u = um[l * 8 + q];
            const float u00r = u[0], u00i = u[1], u01r = u[2], u01i = u[3];
            const float u10r = u[4], u10i = u[5], u11r = u[6], u11i = u[7];
            const int b = 7 - q;
            if (b < 3) {
                const int m = 1 << b;
#pragma unroll
                for (int i0 = 0; i0 < 8; ++i0) {
                    if (i0 & m) continue;
                    const int i1 = i0 | m;
                    const float a0r = sr[i0], a0i = si[i0];
                    const float a1r = sr[i1], a1i = si[i1];
                    float n0r = 0.f, n0i = 0.f, n1r = 0.f, n1i = 0.f;
                    CMADD(n0r, n0i, u00r, u00i, a0r, a0i);
                    CMADD(n0r, n0i, u01r, u01i, a1r, a1i);
                    CMADD(n1r, n1i, u10r, u10i, a0r, a0i);
                    CMADD(n1r, n1i, u11r, u11i, a1r, a1i);
                    sr[i0] = n0r; si[i0] = n0i;
                    sr[i1] = n1r; si[i1] = n1i;
                }
            } else {
                const int pb = 1 << (b - 3);
                const int mbit = (lane >> (b - 3)) & 1;
                const float c0r = mbit ? u10r : u00r, c0i = mbit ? u10i : u00i;
                const float c1r = mbit ? u11r : u01r, c1i = mbit ? u11i : u01i;
#pragma unroll
                for (int i = 0; i < 8; ++i) {
                    const float orr = __shfl_xor_sync(0xffffffffu, sr[i], pb);
                    const float oii = __shfl_xor_sync(0xffffffffu, si[i], pb);
                    const float a0r = mbit ? orr : sr[i], a0i = mbit ? oii : si[i];
                    const float a1r = mbit ? sr[i] : orr, a1i = mbit ? si[i] : oii;
                    float nr = 0.f, ni = 0.f;
                    CMADD(nr, ni, c0r, c0i, a0r, a0i);
                    CMADD(nr, ni, c1r, c1i, a1r, a1i);
                    sr[i] = nr; si[i] = ni;
                }
            }
        }

        // ---- CNOT ring (sequential) ----
        for (int q = 0; q < 8; ++q) {
            const int cbit = 7 - q;
            const int tbit = 7 - ((q + r) & 7);
            if (tbit < 3) {
                const int tm = 1 << tbit;
                if (cbit < 3) {
                    const int cm = 1 << cbit;
#pragma unroll
                    for (int i = 0; i < 8; ++i) {
                        if ((i & cm) && !(i & tm)) {
                            const int p = i | tm;
                            float tr = sr[i], ti = si[i];
                            sr[i] = sr[p]; si[i] = si[p];
                            sr[p] = tr;    si[p] = ti;
                        }
                    }
                } else {
                    if ((lane >> (cbit - 3)) & 1) {
#pragma unroll
                        for (int i = 0; i < 8; ++i) {
                            if (!(i & tm)) {
                                const int p = i | tm;
                                float tr = sr[i], ti = si[i];
                                sr[i] = sr[p]; si[i] = si[p];
                                sr[p] = tr;    si[p] = ti;
                            }
                        }
                    }
                }
            } else {
                const int pb = 1 << (tbit - 3);
                if (cbit < 3) {
                    const int cm = 1 << cbit;
#pragma unroll
                    for (int i = 0; i < 8; ++i) {
                        const float vr = __shfl_xor_sync(0xffffffffu, sr[i], pb);
                        const float vi = __shfl_xor_sync(0xffffffffu, si[i], pb);
                        if (i & cm) { sr[i] = vr; si[i] = vi; }
                    }
                } else {
                    const int csel = (lane >> (cbit - 3)) & 1;
#pragma unroll
                    for (int i = 0; i < 8; ++i) {
                        const float vr = __shfl_xor_sync(0xffffffffu, sr[i], pb);
                        const float vi = __shfl_xor_sync(0xffffffffu, si[i], pb);
                        if (csel) { sr[i] = vr; si[i] = vi; }
                    }
                }
            }
        }
    }

    // ---- Emit Whi + Wlo slice images (st[k] = U[k][j], k = lane*8+i) ----
    //   even popc(j): (w0,w1) = ( Re,  Im);  odd: (w0,w1) = ( Im, -Re)
    const bool odd = (__popc(j) & 1) != 0;
    const int jblock = j >> 6;
    const int koff = (j & 63) * 2;
#pragma unroll
    for (int i = 0; i < 8; ++i) {
        const int k = lane * 8 + i;
        const float W0 = odd ?  si[i] : sr[i];
        const float W1 = odd ? -sr[i] : si[i];
#pragma unroll
        for (int comp = 0; comp < 2; ++comp) {
            const float val = comp ? W1 : W0;
            const __half hi = __float2half_rn(val);
            const __half lo = __float2half_rn(val - __half2float(hi));
            const int c = 2 * k + comp;
            const int chunk = c >> 7, n = c & 127;
            const size_t ghi = (size_t)(chunk * CSLICES + jblock);
            const size_t glo = (size_t)(chunk * CSLICES + 4 + jblock);
            *(__half*)(d_B + (ghi * BROWS + n) * BSTRIDE + koff) = hi;
            *(__half*)(d_B + (glo * BROWS + n) * BSTRIDE + koff) = lo;
        }
    }
}

// ============================================================
// Kernel B: y-build -> fp16 mma.sync GEMM (hand-pipelined) -> z
// 256 threads = 8 warps (2 M x 4 N), warp tile 32x32.
// MT=64, 111.7 KB smem -> 2 CTAs/SM (4 warps/SMSP).
// Explicit 2-bank fragment double buffering (program-order
// prefetch: LDSM(next) issued before MMA(cur) in source).
// z accumulated in smem planes zacc[wn][64][8] to free registers.
// 3-term split: psi = yhi*Whi + ylo*Whi + yhi*Wlo.
// ============================================================

#define LOAD_B(brX, t4) { \
    LDSM4(brX[0], bbase + 0u * (16u * BSTRIDE) + (t4) * 32u); \
    LDSM4(brX[1], bbase + 1u * (16u * BSTRIDE) + (t4) * 32u); }
#define LOAD_AH(ahX, t4) { \
    LDSM4(ahX[0], abase + 0u * (16u * ASTRIDE) + (t4) * 32u); \
    LDSM4(ahX[1], abase + 1u * (16u * ASTRIDE) + (t4) * 32u); }
#define LOAD_AL(alX, t4) { \
    LDSM4(alX[0], abase + 512u + 0u * (16u * ASTRIDE) + (t4) * 32u); \
    LDSM4(alX[1], abase + 512u + 1u * (16u * ASTRIDE) + (t4) * 32u); }
#define MMA_SET(aX, brX) { \
    _Pragma("unroll") \
    for (int mf = 0; mf < 2; ++mf) { \
        _Pragma("unroll") \
        for (int nf = 0; nf < 4; ++nf) \
            MMA16816(acc[mf][nf], (aX)[mf], (brX)[nf >> 1][(nf & 1) * 2], \
                     (brX)[nf >> 1][(nf & 1) * 2 + 1]); } }

__global__ void __launch_bounds__(256, 2) sim_kernel(const float* __restrict__ inp,
                                                     float* __restrict__ out) {
    extern __shared__ __align__(1024) unsigned char smem[];
    const uint32_t sb = smem_u32(smem);
    const uint32_t Ab = sb;
    const uint32_t Bb = sb + ABYTES;
    const uint32_t MB = sb + ABYTES + 2 * BSLICE;
    float* zacc = reinterpret_cast<float*>(smem + ABYTES + 2 * BSLICE + 64);
    const int tid = threadIdx.x;
    const int lane = tid & 31, warp = tid >> 5;
    const int wm = warp & 1, wn = warp >> 1;   // 2 M x 4 N warp grid
    const int b0 = blockIdx.x * MT;

    if (tid == 0) { MBAR_INIT(MB, 1); MBAR_INIT(MB + 8, 1); }
    __syncthreads();
    if (tid == 0) {
        MBAR_EXPECT(MB, BSLICE);     bulk_g2s(Bb,          d_B,          BSLICE, MB);
        MBAR_EXPECT(MB + 8, BSLICE); bulk_g2s(Bb + BSLICE, d_B + BSLICE, BSLICE, MB + 8);
    }

    // zero z accumulator planes
    for (int i = tid; i < 4 * 64 * 8; i += 256) zacc[i] = 0.f;

    // ---- A build: y hi (k 0-255) and lo (k 256-511), fp16; 4 threads/row ----
    {
        const int row = tid >> 2, seg = tid & 3;
        const float4 x0 = *(const float4*)(inp + (size_t)(b0 + row) * 8);
        const float4 x1 = *(const float4*)(inp + (size_t)(b0 + row) * 8 + 4);
        const float xs[8] = {x0.x, x0.y, x0.z, x0.w, x1.x, x1.y, x1.z, x1.w};
        float fc[8], fs[8];
#pragma unroll
        for (int q = 0; q < 8; ++q) __sincosf(0.5f * xs[q], &fs[q], &fc[q]);
        float ph[16], pl[16];
#pragma unroll
        for (int i = 0; i < 16; ++i) {
            ph[i] = ((i & 8) ? fs[0] : fc[0]) * ((i & 4) ? fs[1] : fc[1]) *
                    ((i & 2) ? fs[2] : fc[2]) * ((i & 1) ? fs[3] : fc[3]);
            pl[i] = ((i & 8) ? fs[4] : fc[4]) * ((i & 4) ? fs[5] : fc[5]) *
                    ((i & 2) ? fs[6] : fc[6]) * ((i & 1) ? fs[7] : fc[7]);
        }
        unsigned char* arow = smem + (size_t)row * ASTRIDE;
#pragma unroll 4
        for (int i = 0; i < 64; i += 2) {
            const int jj = seg * 64 + i;
            float y0 = ph[jj >> 4] * pl[jj & 15];
            float y1 = ph[(jj + 1) >> 4] * pl[(jj + 1) & 15];
            if ((__popc(jj) & 3) >= 2)       y0 = -y0;
            if ((__popc(jj + 1) & 3) >= 2)   y1 = -y1;
            const __half h0 = __float2half_rn(y0), h1 = __float2half_rn(y1);
            const __half l0 = __float2half_rn(y0 - __half2float(h0));
            const __half l1 = __float2half_rn(y1 - __half2float(h1));
            __half2 hp; hp.x = h0; hp.y = h1;
            __half2 lp; lp.x = l0; lp.y = l1;
            *(__half2*)(arow + jj * 2)       = hp;
            *(__half2*)(arow + 512 + jj * 2) = lp;
        }
    }
    __syncthreads();

    // invariant per-lane ldmatrix offsets
    const uint32_t aoff = (uint32_t)((wm * 32 + (lane & 7) + ((lane >> 3) & 1) * 8) * ASTRIDE)
                        + ((lane >> 4) & 1) * 16;
    const uint32_t boff = (uint32_t)((wn * 32 + (lane & 7) + ((lane >> 4) & 1) * 8) * BSTRIDE)
                        + ((lane >> 3) & 1) * 16;

    float acc[2][4][4];

#pragma unroll 1
    for (int gs = 0; gs < GSLICES; ++gs) {
        const int chunk = gs >> 3;
        const int s = gs & 7;
        if (s == 0) {
#pragma unroll
            for (int mf = 0; mf < 2; ++mf)
#pragma unroll
                for (int nf = 0; nf < 4; ++nf)
#pragma unroll
                    for (int c = 0; c < 4; ++c) acc[mf][nf][c] = 0.f;
        }

        const uint32_t bar = MB + (uint32_t)(gs & 1) * 8;
        MBAR_WAIT(bar, (gs >> 1) & 1);
        const uint32_t bbase = Bb + (uint32_t)(gs & 1) * BSLICE + boff;
        const int jb = (s < 4) ? s : (s - 4);
        const uint32_t abase = Ab + aoff + (uint32_t)jb * 128u;
        const bool dual = (s < 4);

        // ---- hand-pipelined 4-step k loop, 2 register banks ----
        {
            uint32_t br0[2][4], ah0[2][4], al0[2][4];
            uint32_t br1[2][4], ah1[2][4], al1[2][4];
            LOAD_B(br0, 0); LOAD_AH(ah0, 0); if (dual) LOAD_AL(al0, 0);
            // t4 = 0: prefetch bank1(step1), compute bank0
            LOAD_B(br1, 1); LOAD_AH(ah1, 1); if (dual) LOAD_AL(al1, 1);
            MMA_SET(ah0, br0); if (dual) MMA_SET(al0, br0);
            // t4 = 1: prefetch bank0(step2), compute bank1
            LOAD_B(br0, 2); LOAD_AH(ah0, 2); if (dual) LOAD_AL(al0, 2);
            MMA_SET(ah1, br1); if (dual) MMA_SET(al1, br1);
            // t4 = 2: prefetch bank1(step3), compute bank0
            LOAD_B(br1, 3); LOAD_AH(ah1, 3); if (dual) LOAD_AL(al1, 3);
            MMA_SET(ah0, br0); if (dual) MMA_SET(al0, br0);
            // t4 = 3: compute bank1
            MMA_SET(ah1, br1); if (dual) MMA_SET(al1, br1);
        }

        __syncthreads();
        if (tid == 0 && gs + 2 < GSLICES) {
            MBAR_EXPECT(bar, BSLICE);
            bulk_g2s(Bb + (uint32_t)(gs & 1) * BSLICE,
                     d_B + (size_t)(gs + 2) * BSLICE, BSLICE, bar);
        }

        // chunk epilogue: p = Re^2 + Im^2, fold signs into smem z planes
        if (s == 7) {
#pragma unroll
            for (int mf = 0; mf < 2; ++mf)
#pragma unroll
                for (int rh = 0; rh < 2; ++rh) {
                    const int row = wm * 32 + mf * 16 + (lane >> 2) + rh * 8;
                    float cz[8];
#pragma unroll
                    for (int i = 0; i < 8; ++i) cz[i] = 0.f;
#pragma unroll
                    for (int nf = 0; nf < 4; ++nf) {
                        const float x0 = acc[mf][nf][rh * 2];
                        const float x1 = acc[mf][nf][rh * 2 + 1];
                        const float p = x0 * x0 + x1 * x1;
                        const int k = chunk * 64 + wn * 16 + nf * 4 + (lane & 3);
#pragma unroll
                        for (int i = 0; i < 8; ++i)
                            cz[i] += ((k >> (7 - i)) & 1) ? -p : p;
                    }
#pragma unroll
                    for (int i = 0; i < 8; ++i) {
                        cz[i] += __shfl_down_sync(0xffffffffu, cz[i], 1);
                        cz[i] += __shfl_down_sync(0xffffffffu, cz[i], 2);
                    }
                    if ((lane & 3) == 0) {
                        float* zp = zacc + ((size_t)wn * 64 + row) * 8;
#pragma unroll
                        for (int i = 0; i < 8; ++i) zp[i] += cz[i];
                    }
                }
        }
    }

    // final z reduction across the 4 N-warp planes
    __syncthreads();
    {
        const int r = tid >> 2, o = tid & 3;   // row 0..63, comp pair 0..3
        float2 sum = make_float2(0.f, 0.f);
#pragma unroll
        for (int wnn = 0; wnn < 4; ++wnn) {
            const float* zp = zacc + ((size_t)wnn * 64 + r) * 8 + o * 2;
            sum.x += zp[0];
            sum.y += zp[1];
        }
        *(float2*)(out + (size_t)(b0 + r) * 8 + o * 2) = sum;
    }
}

// ============================================================
extern "C" void kernel_launch(void* const* d_in, const int* in_sizes, int n_in,
                              void* d_out, int out_size) {
    const float* inputs  = (const float*)d_in[0];  // (65536, 8) float32
    const float* weights = (const float*)d_in[1];  // (6, 8, 3) float32
    float* out = (float*)d_out;                    // (65536, 8) float32

    const int B = in_sizes[0] / NQ;

    static int configured = 0;
    if (!configured) {
        cudaFuncSetAttribute(sim_kernel, cudaFuncAttributeMaxDynamicSharedMemorySize, SMEM_TOTAL);
        configured = 1;
    }

    build_U_kernel<<<32, 256>>>(weights);
    sim_kernel<<<B / MT, 256, SMEM_TOTAL>>>(inputs, out);
}

// round 13
// speedup vs baseline: 1.2043x; 1.2043x over previous
#include <cuda_runtime.h>
#include <cuda_fp16.h>
#include <cstdint>

#define NQ      8
#define DIM     256
#define MT      64               // batch rows per CTA
#define NCHUNK  4                // N processed in 4 chunks of 128 cols
#define CSLICES 8                // per chunk: s0-3 fp16 Whi (K=64 ea), s4-7 int8 (K=128 ea)
#define GSLICES 32
#define BSTRIDE 144              // B smem row: 128 B data + 16 B pad
#define BROWS   128
#define BSLICE  (BROWS * BSTRIDE)   // 18432 B per slice
#define ASTRIDE 528              // A row: 512 B data + 16 B pad (both fp16 and int8 A)
#define A16OFF  0
#define A8OFF   (MT * ASTRIDE)               // 33792
#define BOFF    (2 * MT * ASTRIDE)           // 67584
#define MBOFF   (BOFF + 2 * BSLICE)          // 104448
#define ZOFF    (MBOFF + 64)                 // 104512
#define SMEM_TOTAL (ZOFF + 4 * 64 * 8 * 4)   // 112704  (2 CTAs/SM)

// int8 correction scale: term = ql*QWh + qy*QWl, weight 1/(4096*127^2)
#define S_CORR  (1.0f / 66064384.0f)

// W slice images. Slice gs = chunk*8 + s:
//  s0-3: fp16 Whi, j in [s*64, s*64+64), row n (0..127) = output col, (j&63)*2 byte
//  s4-5: int8 QWh, j in [(s-4)*128, +128): byte (j&127)
//  s6-7: int8 QWl, j in [(s-6)*128, +128)
__device__ __align__(128) unsigned char d_B[GSLICES * BSLICE];  // 589824 B

// ---------------- helpers ----------------
__device__ __forceinline__ uint32_t smem_u32(const void* p) {
    uint32_t a;
    asm("{ .reg .u64 t; cvta.to.shared.u64 t, %1; cvt.u32.u64 %0, t; }" : "=r"(a) : "l"(p));
    return a;
}

#define MBAR_INIT(a, n)  asm volatile("mbarrier.init.shared.b64 [%0], %1;" :: "r"(a), "r"((uint32_t)(n)) : "memory")
#define MBAR_EXPECT(a, n) asm volatile("mbarrier.arrive.expect_tx.shared.b64 _, [%0], %1;" :: "r"(a), "r"((uint32_t)(n)) : "memory")
#define MBAR_WAIT(a, ph) do {                                                        \
    uint32_t _m = (a), _p = (ph), _d;                                                \
    asm volatile("{ .reg .pred p; mbarrier.try_wait.parity.acquire.cta.shared::cta.b64 p, [%1], %2; selp.b32 %0,1,0,p; }" \
                 : "=r"(_d) : "r"(_m), "r"(_p) : "memory");                          \
    if (!_d) {                                                                       \
        asm volatile("{ .reg .pred P1; W%=: mbarrier.try_wait.parity.acquire.cta.shared::cta.b64 P1, [%0], %1, 0x989680;" \
                     " @P1 bra.uni D%=; bra.uni W%=; D%=: }" :: "r"(_m), "r"(_p) : "memory"); \
    }                                                                                \
} while (0)

__device__ __forceinline__ void bulk_g2s(uint32_t dst, const void* src, uint32_t bytes, uint32_t mbar) {
    asm volatile("cp.async.bulk.shared::cluster.global.mbarrier::complete_tx::bytes [%0], [%1], %2, [%3];"
        :: "r"(dst), "l"(src), "r"(bytes), "r"(mbar) : "memory");
}

#define LDSM4(r, addr) \
    asm volatile("ldmatrix.sync.aligned.m8n8.x4.shared.b16 {%0,%1,%2,%3}, [%4];" \
        : "=r"((r)[0]), "=r"((r)[1]), "=r"((r)[2]), "=r"((r)[3]) : "r"(addr))

#define MMA16816(c, a, bb0, bb1) \
    asm volatile("mma.sync.aligned.m16n8k16.row.col.f32.f16.f16.f32 " \
        "{%0,%1,%2,%3}, {%4,%5,%6,%7}, {%8,%9}, {%0,%1,%2,%3};" \
        : "+f"((c)[0]), "+f"((c)[1]), "+f"((c)[2]), "+f"((c)[3]) \
        : "r"((a)[0]), "r"((a)[1]), "r"((a)[2]), "r"((a)[3]), "r"(bb0), "r"(bb1))

#define IMMA16832(c, a, bb0, bb1) \
    asm volatile("mma.sync.aligned.m16n8k32.row.col.s32.s8.s8.s32 " \
        "{%0,%1,%2,%3}, {%4,%5,%6,%7}, {%8,%9}, {%0,%1,%2,%3};" \
        : "+r"((c)[0]), "+r"((c)[1]), "+r"((c)[2]), "+r"((c)[3]) \
        : "r"((a)[0]), "r"((a)[1]), "r"((a)[2]), "r"((a)[3]), "r"(bb0), "r"(bb1))

__device__ __forceinline__ uint32_t lds32(uint32_t addr) {
    uint32_t v;
    asm volatile("ld.shared.b32 %0, [%1];" : "=r"(v) : "r"(addr));
    return v;
}

// ============================================================
// Kernel A: build U column j (proven block-per-column version);
// emit fp16 Whi + int8 QWh/QWl slice images.
// ============================================================
__device__ __forceinline__ float2 cmul(float2 a, float2 b) {
    return make_float2(a.x * b.x - a.y * b.y, a.x * b.y + a.y * b.x);
}
__device__ __forceinline__ float2 cadd(float2 a, float2 b) {
    return make_float2(a.x + b.x, a.y + b.y);
}

__global__ void build_U_kernel(const float* __restrict__ w) {
    __shared__ float2 st[DIM];
    const int j = blockIdx.x;
    const int t = threadIdx.x;  // 0..127

    st[t]       = make_float2(t == j ? 1.f : 0.f, 0.f);
    st[t + 128] = make_float2((t + 128) == j ? 1.f : 0.f, 0.f);
    __syncthreads();

    for (int l = 0; l < 6; ++l) {
        const int r = l % (NQ - 1) + 1;
        for (int q = 0; q < NQ; ++q) {
            const float phi = w[(l * NQ + q) * 3 + 0];
            const float th  = w[(l * NQ + q) * 3 + 1];
            const float om  = w[(l * NQ + q) * 3 + 2];
            const float ct = cosf(0.5f * th), sth = sinf(0.5f * th);
            const float a  = 0.5f * (phi + om), bb = 0.5f * (phi - om);
            const float ca = cosf(a),  sa = sinf(a);
            const float cb = cosf(bb), sb = sinf(bb);
            const float2 u00 = make_float2( ca * ct, -sa * ct);
            const float2 u01 = make_float2(-cb * sth, -sb * sth);
            const float2 u10 = make_float2( cb * sth, -sb * sth);
            const float2 u11 = make_float2( ca * ct,  sa * ct);

            const int b    = 7 - q;
            const int mask = 1 << b;
            const int low  = t & (mask - 1);
            const int k0   = ((t >> b) << (b + 1)) | low;
            const int k1   = k0 | mask;
            const float2 a0 = st[k0], a1 = st[k1];
            st[k0] = cadd(cmul(u00, a0), cmul(u01, a1));
            st[k1] = cadd(cmul(u10, a0), cmul(u11, a1));
            __syncthreads();
        }
        for (int q = 0; q < NQ; ++q) {
            const int tq = (q + r) % NQ;
            const int cb = 7 - q;
            const int tb = 7 - tq;
            if (t < 64) {
                const int plo = cb < tb ? cb : tb;
                const int phi_ = cb < tb ? tb : cb;
                const int low  = t & ((1 << plo) - 1);
                const int mid  = (t >> plo) & ((1 << (phi_ - plo - 1)) - 1);
                const int high = t >> (phi_ - 1);
                const int k0   = low | (mid << (plo + 1)) | (high << (phi_ + 1));
                const int k    = k0 | (1 << cb);
                const int p    = k  | (1 << tb);
                const float2 tmp = st[k];
                st[k] = st[p];
                st[p] = tmp;
            }
            __syncthreads();
        }
    }

    // Emit slice images for this j (st[k] = U[k][j]).
    //   even popc(j): (w0,w1) = ( Re,  Im);  odd: (w0,w1) = ( Im, -Re)
    const bool odd = (__popc(j) & 1) != 0;
#pragma unroll
    for (int h = 0; h < 2; ++h) {
        const int kst = t + h * 128;
        const float2 u = st[kst];
        const float W0 = odd ?  u.y : u.x;
        const float W1 = odd ? -u.x : u.y;
#pragma unroll
        for (int comp = 0; comp < 2; ++comp) {
            const float val = comp ? W1 : W0;
            const __half hi = __float2half_rn(val);
            const float hif = __half2float(hi);
            const float lo = val - hif;
            const int c = 2 * kst + comp;
            const int chunk = c >> 7, n = c & 127;
            // fp16 Whi
            *(__half*)(d_B + ((size_t)(chunk * 8 + (j >> 6)) * BSLICE)
                        + (size_t)n * BSTRIDE + (j & 63) * 2) = hi;
            // int8 QWh = rn(Wh*127)
            const int qwh = __float2int_rn(hif * 127.0f);
            *(char*)(d_B + ((size_t)(chunk * 8 + 4 + (j >> 7)) * BSLICE)
                        + (size_t)n * BSTRIDE + (j & 127)) = (char)qwh;
            // int8 QWl = rn(Wl*4096*127)
            const int qwl = __float2int_rn(lo * 520192.0f);
            *(char*)(d_B + ((size_t)(chunk * 8 + 6 + (j >> 7)) * BSLICE)
                        + (size_t)n * BSTRIDE + (j & 127)) = (char)qwl;
        }
    }
}

// ============================================================
// Kernel B: y-build -> mixed fp16/int8 mma.sync GEMM -> z
// 256 threads = 8 warps (2 M x 4 N), warp tile 32x32.
// MT=64, 112.7 KB smem -> 2 CTAs/SM.
// psi = yh*Wh  (fp16, K=256, slices 0-3 per chunk)
//     + [ql|qy]*[QWh;QWl]*S  (int8, K=512, slices 4-7 per chunk)
// ============================================================
__global__ void __launch_bounds__(256, 2) sim_kernel(const float* __restrict__ inp,
                                                     float* __restrict__ out) {
    extern __shared__ __align__(1024) unsigned char smem[];
    const uint32_t sb = smem_u32(smem);
    const uint32_t A16b = sb + A16OFF;
    const uint32_t A8b  = sb + A8OFF;
    const uint32_t Bb   = sb + BOFF;
    const uint32_t MB   = sb + MBOFF;
    float* zacc = reinterpret_cast<float*>(smem + ZOFF);
    const int tid = threadIdx.x;
    const int lane = tid & 31, warp = tid >> 5;
    const int wm = warp & 1, wn = warp >> 1;   // 2 M x 4 N warp grid
    const int b0 = blockIdx.x * MT;

    if (tid == 0) { MBAR_INIT(MB, 1); MBAR_INIT(MB + 8, 1); }
    __syncthreads();
    if (tid == 0) {
        MBAR_EXPECT(MB, BSLICE);     bulk_g2s(Bb,          d_B,          BSLICE, MB);
        MBAR_EXPECT(MB + 8, BSLICE); bulk_g2s(Bb + BSLICE, d_B + BSLICE, BSLICE, MB + 8);
    }

    // zero z accumulator planes
    for (int i = tid; i < 4 * 64 * 8; i += 256) zacc[i] = 0.f;

    // ---- A build: yh fp16 (K=256) + int8 [ql | qy]; 4 threads/row ----
    {
        const int row = tid >> 2, seg = tid & 3;
        const float4 x0 = *(const float4*)(inp + (size_t)(b0 + row) * 8);
        const float4 x1 = *(const float4*)(inp + (size_t)(b0 + row) * 8 + 4);
        const float xs[8] = {x0.x, x0.y, x0.z, x0.w, x1.x, x1.y, x1.z, x1.w};
        float fc[8], fs[8];
#pragma unroll
        for (int q = 0; q < 8; ++q) sincosf(0.5f * xs[q], &fs[q], &fc[q]);
        float ph[16], pl[16];
#pragma unroll
        for (int i = 0; i < 16; ++i) {
            ph[i] = ((i & 8) ? fs[0] : fc[0]) * ((i & 4) ? fs[1] : fc[1]) *
                    ((i & 2) ? fs[2] : fc[2]) * ((i & 1) ? fs[3] : fc[3]);
            pl[i] = ((i & 8) ? fs[4] : fc[4]) * ((i & 4) ? fs[5] : fc[5]) *
                    ((i & 2) ? fs[6] : fc[6]) * ((i & 1) ? fs[7] : fc[7]);
        }
        unsigned char* a16 = smem + A16OFF + (size_t)row * ASTRIDE;
        unsigned char* a8  = smem + A8OFF  + (size_t)row * ASTRIDE;
#pragma unroll 4
        for (int i = 0; i < 64; i += 2) {
            const int jj = seg * 64 + i;
            float y0 = ph[jj >> 4] * pl[jj & 15];
            float y1 = ph[(jj + 1) >> 4] * pl[(jj + 1) & 15];
            if ((__popc(jj) & 3) >= 2)       y0 = -y0;
            if ((__popc(jj + 1) & 3) >= 2)   y1 = -y1;
            const __half h0 = __float2half_rn(y0), h1 = __float2half_rn(y1);
            const float h0f = __half2float(h0), h1f = __half2float(h1);
            __half2 hp; hp.x = h0; hp.y = h1;
            *(__half2*)(a16 + jj * 2) = hp;
            // ql = rn(yl * 4096 * 127), qy = rn(y * 127)
            const int ql0 = __float2int_rn((y0 - h0f) * 520192.0f);
            const int ql1 = __float2int_rn((y1 - h1f) * 520192.0f);
            const int qy0 = __float2int_rn(y0 * 127.0f);
            const int qy1 = __float2int_rn(y1 * 127.0f);
            *(unsigned short*)(a8 + jj) =
                (unsigned short)(((unsigned)(unsigned char)(char)ql0) |
                                 (((unsigned)(unsigned char)(char)ql1) << 8));
            *(unsigned short*)(a8 + 256 + jj) =
                (unsigned short)(((unsigned)(unsigned char)(char)qy0) |
                                 (((unsigned)(unsigned char)(char)qy1) << 8));
        }
    }
    __syncthreads();

    // invariant per-lane offsets
    const uint32_t aoff16 = (uint32_t)((wm * 32 + (lane & 7) + ((lane >> 3) & 1) * 8) * ASTRIDE)
                          + ((lane >> 4) & 1) * 16;
    const uint32_t boff16 = (uint32_t)((wn * 32 + (lane & 7) + ((lane >> 4) & 1) * 8) * BSTRIDE)
                          + ((lane >> 3) & 1) * 16;
    const uint32_t aoff8  = (uint32_t)((wm * 32 + (lane >> 2)) * ASTRIDE) + (lane & 3) * 4;
    const uint32_t boff8  = (uint32_t)((wn * 32 + (lane >> 2)) * BSTRIDE) + (lane & 3) * 4;

    float accf[2][4][4];
    int   acci[2][4][4];

#pragma unroll 1
    for (int gs = 0; gs < GSLICES; ++gs) {
        const int chunk = gs >> 3;
        const int s = gs & 7;
        if (s == 0) {
#pragma unroll
            for (int mf = 0; mf < 2; ++mf)
#pragma unroll
                for (int nf = 0; nf < 4; ++nf)
#pragma unroll
                    for (int c = 0; c < 4; ++c) { accf[mf][nf][c] = 0.f; acci[mf][nf][c] = 0; }
        }

        const uint32_t bar = MB + (uint32_t)(gs & 1) * 8;
        MBAR_WAIT(bar, (gs >> 1) & 1);
        const uint32_t bbuf = Bb + (uint32_t)(gs & 1) * BSLICE;

        if (s < 4) {
            // ---- fp16 slice: K=64 of yh*Wh ----
            const uint32_t bbase = bbuf + boff16;
            const uint32_t abase = A16b + aoff16 + (uint32_t)s * 128u;
#pragma unroll
            for (int t4 = 0; t4 < 4; ++t4) {
                uint32_t br[2][4], a[2][4];
#pragma unroll
                for (int nb = 0; nb < 2; ++nb)
                    LDSM4(br[nb], bbase + (uint32_t)nb * (16u * BSTRIDE) + (uint32_t)t4 * 32u);
#pragma unroll
                for (int mf = 0; mf < 2; ++mf)
                    LDSM4(a[mf], abase + (uint32_t)mf * (16u * ASTRIDE) + (uint32_t)t4 * 32u);
#pragma unroll
                for (int mf = 0; mf < 2; ++mf)
#pragma unroll
                    for (int nf = 0; nf < 4; ++nf)
                        MMA16816(accf[mf][nf], a[mf], br[nf >> 1][(nf & 1) * 2],
                                 br[nf >> 1][(nf & 1) * 2 + 1]);
            }
        } else {
            // ---- int8 slice: K=128 of [ql|qy]*[QWh;QWl] ----
            const uint32_t kw = (uint32_t)(s - 4) * 128u;
#pragma unroll
            for (int t4 = 0; t4 < 4; ++t4) {
                const uint32_t kb = kw + (uint32_t)t4 * 32u;
                uint32_t b0[4], b1[4];
#pragma unroll
                for (int nf = 0; nf < 4; ++nf) {
                    const uint32_t ba = bbuf + boff8 + (uint32_t)nf * (8u * BSTRIDE) + (kb & 127u);
                    b0[nf] = lds32(ba);
                    b1[nf] = lds32(ba + 16u);
                }
#pragma unroll
                for (int mf = 0; mf < 2; ++mf) {
                    const uint32_t aa = A8b + aoff8 + (uint32_t)mf * (16u * ASTRIDE) + kb;
                    uint32_t a[4];
                    a[0] = lds32(aa);
                    a[1] = lds32(aa + 8u * ASTRIDE);
                    a[2] = lds32(aa + 16u);
                    a[3] = lds32(aa + 8u * ASTRIDE + 16u);
#pragma unroll
                    for (int nf = 0; nf < 4; ++nf)
                        IMMA16832(acci[mf][nf], a, b0[nf], b1[nf]);
                }
            }
        }

        __syncthreads();
        if (tid == 0 && gs + 2 < GSLICES) {
            MBAR_EXPECT(bar, BSLICE);
            bulk_g2s(Bb + (uint32_t)(gs & 1) * BSLICE,
                     d_B + (size_t)(gs + 2) * BSLICE, BSLICE, bar);
        }

        // chunk epilogue: psi = accf + S*acci; p; fold signs into zacc
        if (s == 7) {
#pragma unroll
            for (int mf = 0; mf < 2; ++mf)
#pragma unroll
                for (int rh = 0; rh < 2; ++rh) {
                    const int row = wm * 32 + mf * 16 + (lane >> 2) + rh * 8;
                    float cz[8];
#pragma unroll
                    for (int i = 0; i < 8; ++i) cz[i] = 0.f;
#pragma unroll
                    for (int nf = 0; nf < 4; ++nf) {
                        const float x0 = accf[mf][nf][rh * 2]     + S_CORR * (float)acci[mf][nf][rh * 2];
                        const float x1 = accf[mf][nf][rh * 2 + 1] + S_CORR * (float)acci[mf][nf][rh * 2 + 1];
                        const float p = x0 * x0 + x1 * x1;
                        const int k = chunk * 64 + wn * 16 + nf * 4 + (lane & 3);
#pragma unroll
                        for (int i = 0; i < 8; ++i)
                            cz[i] += ((k >> (7 - i)) & 1) ? -p : p;
                    }
#pragma unroll
                    for (int i = 0; i < 8; ++i) {
                        cz[i] += __shfl_down_sync(0xffffffffu, cz[i], 1);
                        cz[i] += __shfl_down_sync(0xffffffffu, cz[i], 2);
                    }
                    if ((lane & 3) == 0) {
                        float* zp = zacc + ((size_t)wn * 64 + row) * 8;
#pragma unroll
                        for (int i = 0; i < 8; ++i) zp[i] += cz[i];
                    }
                }
        }
    }

    // final z reduction across the 4 N-warp planes
    __syncthreads();
    {
        const int r = tid >> 2, o = tid & 3;   // row 0..63, comp pair 0..3
        float2 sum = make_float2(0.f, 0.f);
#pragma unroll
        for (int wnn = 0; wnn < 4; ++wnn) {
            const float* zp = zacc + ((size_t)wnn * 64 + r) * 8 + o * 2;
            sum.x += zp[0];
            sum.y += zp[1];
        }
        *(float2*)(out + (size_t)(b0 + r) * 8 + o * 2) = sum;
    }
}

// ============================================================
extern "C" void kernel_launch(void* const* d_in, const int* in_sizes, int n_in,
                              void* d_out, int out_size) {
    const float* inputs  = (const float*)d_in[0];  // (65536, 8) float32
    const float* weights = (const float*)d_in[1];  // (6, 8, 3) float32
    float* out = (float*)d_out;                    // (65536, 8) float32

    const int B = in_sizes[0] / NQ;

    static int configured = 0;
    if (!configured) {
        cudaFuncSetAttribute(sim_kernel, cudaFuncAttributeMaxDynamicSharedMemorySize, SMEM_TOTAL);
        configured = 1;
    }

    build_U_kernel<<<DIM, 128>>>(weights);
    sim_kernel<<<B / MT, 256, SMEM_TOTAL>>>(inputs, out);
}

// round 15
// speedup vs baseline: 1.2323x; 1.0233x over previous
#include <cuda_runtime.h>
#include <cuda_fp16.h>
#include <cstdint>

#define NQ      8
#define DIM     256
#define MT      64               // batch rows per CTA
#define NCHUNK  4                // N processed in 4 chunks of 128 cols
#define CSLICES 8                // per chunk: s0-3 fp16 Whi (K=64 ea), s4-7 int8 (K=128 ea)
#define GSLICES 32
#define BSTRIDE 144              // B smem row: 128 B data + 16 B pad
#define BROWS   128
#define BSLICE  (BROWS * BSTRIDE)   // 18432 B per slice
#define ASTRIDE 528              // A row: 512 B data + 16 B pad (both fp16 and int8 A)
#define A16OFF  0
#define A8OFF   (MT * ASTRIDE)               // 33792
#define BOFF    (2 * MT * ASTRIDE)           // 67584
#define MBOFF   (BOFF + 2 * BSLICE)          // 104448
#define ZOFF    (MBOFF + 64)                 // 104512
#define SMEM_TOTAL (ZOFF + 4 * 64 * 8 * 4)   // 112704  (2 CTAs/SM)

// int8 correction scale: term = ql*QWh + qy*QWl, weight 1/(4096*127^2)
#define S_CORR  (1.0f / 66064384.0f)

// W slice images. Slice gs = chunk*8 + s:
//  s0-3: fp16 Whi, j in [s*64, s*64+64), row n (0..127) = output col, (j&63)*2 byte
//  s4-5: int8 QWh, j in [(s-4)*128, +128): byte (j&127)
//  s6-7: int8 QWl, j in [(s-6)*128, +128)
__device__ __align__(128) unsigned char d_B[GSLICES * BSLICE];  // 589824 B

// ---------------- helpers ----------------
__device__ __forceinline__ uint32_t smem_u32(const void* p) {
    uint32_t a;
    asm("{ .reg .u64 t; cvta.to.shared.u64 t, %1; cvt.u32.u64 %0, t; }" : "=r"(a) : "l"(p));
    return a;
}

#define MBAR_INIT(a, n)  asm volatile("mbarrier.init.shared.b64 [%0], %1;" :: "r"(a), "r"((uint32_t)(n)) : "memory")
#define MBAR_EXPECT(a, n) asm volatile("mbarrier.arrive.expect_tx.shared.b64 _, [%0], %1;" :: "r"(a), "r"((uint32_t)(n)) : "memory")
#define MBAR_WAIT(a, ph) do {                                                        \
    uint32_t _m = (a), _p = (ph), _d;                                                \
    asm volatile("{ .reg .pred p; mbarrier.try_wait.parity.acquire.cta.shared::cta.b64 p, [%1], %2; selp.b32 %0,1,0,p; }" \
                 : "=r"(_d) : "r"(_m), "r"(_p) : "memory");                          \
    if (!_d) {                                                                       \
        asm volatile("{ .reg .pred P1; W%=: mbarrier.try_wait.parity.acquire.cta.shared::cta.b64 P1, [%0], %1, 0x989680;" \
                     " @P1 bra.uni D%=; bra.uni W%=; D%=: }" :: "r"(_m), "r"(_p) : "memory"); \
    }                                                                                \
} while (0)

__device__ __forceinline__ void bulk_g2s(uint32_t dst, const void* src, uint32_t bytes, uint32_t mbar) {
    asm volatile("cp.async.bulk.shared::cluster.global.mbarrier::complete_tx::bytes [%0], [%1], %2, [%3];"
        :: "r"(dst), "l"(src), "r"(bytes), "r"(mbar) : "memory");
}

#define LDSM4(r, addr) \
    asm volatile("ldmatrix.sync.aligned.m8n8.x4.shared.b16 {%0,%1,%2,%3}, [%4];" \
        : "=r"((r)[0]), "=r"((r)[1]), "=r"((r)[2]), "=r"((r)[3]) : "r"(addr))

#define MMA16816(c, a, bb0, bb1) \
    asm volatile("mma.sync.aligned.m16n8k16.row.col.f32.f16.f16.f32 " \
        "{%0,%1,%2,%3}, {%4,%5,%6,%7}, {%8,%9}, {%0,%1,%2,%3};" \
        : "+f"((c)[0]), "+f"((c)[1]), "+f"((c)[2]), "+f"((c)[3]) \
        : "r"((a)[0]), "r"((a)[1]), "r"((a)[2]), "r"((a)[3]), "r"(bb0), "r"(bb1))

#define IMMA16832(c, a, bb0, bb1) \
    asm volatile("mma.sync.aligned.m16n8k32.row.col.s32.s8.s8.s32 " \
        "{%0,%1,%2,%3}, {%4,%5,%6,%7}, {%8,%9}, {%0,%1,%2,%3};" \
        : "+r"((c)[0]), "+r"((c)[1]), "+r"((c)[2]), "+r"((c)[3]) \
        : "r"((a)[0]), "r"((a)[1]), "r"((a)[2]), "r"((a)[3]), "r"(bb0), "r"(bb1))

// ============================================================
// Kernel A: build U column j (proven block-per-column version);
// emit fp16 Whi + int8 QWh/QWl slice images.
// ============================================================
__device__ __forceinline__ float2 cmul(float2 a, float2 b) {
    return make_float2(a.x * b.x - a.y * b.y, a.x * b.y + a.y * b.x);
}
__device__ __forceinline__ float2 cadd(float2 a, float2 b) {
    return make_float2(a.x + b.x, a.y + b.y);
}

__global__ void build_U_kernel(const float* __restrict__ w) {
    __shared__ float2 st[DIM];
    const int j = blockIdx.x;
    const int t = threadIdx.x;  // 0..127

    st[t]       = make_float2(t == j ? 1.f : 0.f, 0.f);
    st[t + 128] = make_float2((t + 128) == j ? 1.f : 0.f, 0.f);
    __syncthreads();

    for (int l = 0; l < 6; ++l) {
        const int r = l % (NQ - 1) + 1;
        for (int q = 0; q < NQ; ++q) {
            const float phi = w[(l * NQ + q) * 3 + 0];
            const float th  = w[(l * NQ + q) * 3 + 1];
            const float om  = w[(l * NQ + q) * 3 + 2];
            const float ct = cosf(0.5f * th), sth = sinf(0.5f * th);
            const float a  = 0.5f * (phi + om), bb = 0.5f * (phi - om);
            const float ca = cosf(a),  sa = sinf(a);
            const float cb = cosf(bb), sb = sinf(bb);
            const float2 u00 = make_float2( ca * ct, -sa * ct);
            const float2 u01 = make_float2(-cb * sth, -sb * sth);
            const float2 u10 = make_float2( cb * sth, -sb * sth);
            const float2 u11 = make_float2( ca * ct,  sa * ct);

            const int b    = 7 - q;
            const int mask = 1 << b;
            const int low  = t & (mask - 1);
            const int k0   = ((t >> b) << (b + 1)) | low;
            const int k1   = k0 | mask;
            const float2 a0 = st[k0], a1 = st[k1];
            st[k0] = cadd(cmul(u00, a0), cmul(u01, a1));
            st[k1] = cadd(cmul(u10, a0), cmul(u11, a1));
            __syncthreads();
        }
        for (int q = 0; q < NQ; ++q) {
            const int tq = (q + r) % NQ;
            const int cb = 7 - q;
            const int tb = 7 - tq;
            if (t < 64) {
                const int plo = cb < tb ? cb : tb;
                const int phi_ = cb < tb ? tb : cb;
                const int low  = t & ((1 << plo) - 1);
                const int mid  = (t >> plo) & ((1 << (phi_ - plo - 1)) - 1);
                const int high = t >> (phi_ - 1);
                const int k0   = low | (mid << (plo + 1)) | (high << (phi_ + 1));
                const int k    = k0 | (1 << cb);
                const int p    = k  | (1 << tb);
                const float2 tmp = st[k];
                st[k] = st[p];
                st[p] = tmp;
            }
            __syncthreads();
        }
    }

    // Emit slice images for this j (st[k] = U[k][j]).
    //   even popc(j): (w0,w1) = ( Re,  Im);  odd: (w0,w1) = ( Im, -Re)
    const bool odd = (__popc(j) & 1) != 0;
#pragma unroll
    for (int h = 0; h < 2; ++h) {
        const int kst = t + h * 128;
        const float2 u = st[kst];
        const float W0 = odd ?  u.y : u.x;
        const float W1 = odd ? -u.x : u.y;
#pragma unroll
        for (int comp = 0; comp < 2; ++comp) {
            const float val = comp ? W1 : W0;
            const __half hi = __float2half_rn(val);
            const float hif = __half2float(hi);
            const float lo = val - hif;
            const int c = 2 * kst + comp;
            const int chunk = c >> 7, n = c & 127;
            // fp16 Whi
            *(__half*)(d_B + ((size_t)(chunk * 8 + (j >> 6)) * BSLICE)
                        + (size_t)n * BSTRIDE + (j & 63) * 2) = hi;
            // int8 QWh = rn(Wh*127)
            const int qwh = __float2int_rn(hif * 127.0f);
            *(char*)(d_B + ((size_t)(chunk * 8 + 4 + (j >> 7)) * BSLICE)
                        + (size_t)n * BSTRIDE + (j & 127)) = (char)qwh;
            // int8 QWl = rn(Wl*4096*127)
            const int qwl = __float2int_rn(lo * 520192.0f);
            *(char*)(d_B + ((size_t)(chunk * 8 + 6 + (j >> 7)) * BSLICE)
                        + (size_t)n * BSTRIDE + (j & 127)) = (char)qwl;
        }
    }
}

// ============================================================
// Kernel B: y-build -> mixed fp16/int8 mma.sync GEMM -> z
// 256 threads = 8 warps (2 M x 4 N), warp tile 32x32.
// MT=64, 112.7 KB smem -> 2 CTAs/SM.
// psi = yh*Wh  (fp16, K=256, slices 0-3 per chunk)
//     + [ql|qy]*[QWh;QWl]*S  (int8, K=512, slices 4-7 per chunk)
// int8 fragments loaded via ldmatrix.b16 (4-byte int8 groups = b16
// column pairs): A x4 covers (rows0-7,+0)(rows8-15,+0)(rows0-7,+16)
// (rows8-15,+16) = a0..a3; B x4 covers b0,b1 of two 8-n blocks.
// ============================================================
__global__ void __launch_bounds__(256, 2) sim_kernel(const float* __restrict__ inp,
                                                     float* __restrict__ out) {
    extern __shared__ __align__(1024) unsigned char smem[];
    const uint32_t sb = smem_u32(smem);
    const uint32_t A16b = sb + A16OFF;
    const uint32_t A8b  = sb + A8OFF;
    const uint32_t Bb   = sb + BOFF;
    const uint32_t MB   = sb + MBOFF;
    float* zacc = reinterpret_cast<float*>(smem + ZOFF);
    const int tid = threadIdx.x;
    const int lane = tid & 31, warp = tid >> 5;
    const int wm = warp & 1, wn = warp >> 1;   // 2 M x 4 N warp grid
    const int b0 = blockIdx.x * MT;

    if (tid == 0) { MBAR_INIT(MB, 1); MBAR_INIT(MB + 8, 1); }
    __syncthreads();
    if (tid == 0) {
        MBAR_EXPECT(MB, BSLICE);     bulk_g2s(Bb,          d_B,          BSLICE, MB);
        MBAR_EXPECT(MB + 8, BSLICE); bulk_g2s(Bb + BSLICE, d_B + BSLICE, BSLICE, MB + 8);
    }

    // zero z accumulator planes
    for (int i = tid; i < 4 * 64 * 8; i += 256) zacc[i] = 0.f;

    // ---- A build: yh fp16 (K=256) + int8 [ql | qy]; 4 threads/row ----
    {
        const int row = tid >> 2, seg = tid & 3;
        const float4 x0 = *(const float4*)(inp + (size_t)(b0 + row) * 8);
        const float4 x1 = *(const float4*)(inp + (size_t)(b0 + row) * 8 + 4);
        const float xs[8] = {x0.x, x0.y, x0.z, x0.w, x1.x, x1.y, x1.z, x1.w};
        float fc[8], fs[8];
#pragma unroll
        for (int q = 0; q < 8; ++q) sincosf(0.5f * xs[q], &fs[q], &fc[q]);
        float ph[16], pl[16];
#pragma unroll
        for (int i = 0; i < 16; ++i) {
            ph[i] = ((i & 8) ? fs[0] : fc[0]) * ((i & 4) ? fs[1] : fc[1]) *
                    ((i & 2) ? fs[2] : fc[2]) * ((i & 1) ? fs[3] : fc[3]);
            pl[i] = ((i & 8) ? fs[4] : fc[4]) * ((i & 4) ? fs[5] : fc[5]) *
                    ((i & 2) ? fs[6] : fc[6]) * ((i & 1) ? fs[7] : fc[7]);
        }
        unsigned char* a16 = smem + A16OFF + (size_t)row * ASTRIDE;
        unsigned char* a8  = smem + A8OFF  + (size_t)row * ASTRIDE;
#pragma unroll 4
        for (int i = 0; i < 64; i += 2) {
            const int jj = seg * 64 + i;
            float y0 = ph[jj >> 4] * pl[jj & 15];
            float y1 = ph[(jj + 1) >> 4] * pl[(jj + 1) & 15];
            if ((__popc(jj) & 3) >= 2)       y0 = -y0;
            if ((__popc(jj + 1) & 3) >= 2)   y1 = -y1;
            const __half h0 = __float2half_rn(y0), h1 = __float2half_rn(y1);
            const float h0f = __half2float(h0), h1f = __half2float(h1);
            __half2 hp; hp.x = h0; hp.y = h1;
            *(__half2*)(a16 + jj * 2) = hp;
            // ql = rn(yl * 4096 * 127), qy = rn(y * 127)
            const int ql0 = __float2int_rn((y0 - h0f) * 520192.0f);
            const int ql1 = __float2int_rn((y1 - h1f) * 520192.0f);
            const int qy0 = __float2int_rn(y0 * 127.0f);
            const int qy1 = __float2int_rn(y1 * 127.0f);
            *(unsigned short*)(a8 + jj) =
                (unsigned short)(((unsigned)(unsigned char)(char)ql0) |
                                 (((unsigned)(unsigned char)(char)ql1) << 8));
            *(unsigned short*)(a8 + 256 + jj) =
                (unsigned short)(((unsigned)(unsigned char)(char)qy0) |
                                 (((unsigned)(unsigned char)(char)qy1) << 8));
        }
    }
    __syncthreads();

    // invariant per-lane offsets
    const uint32_t aoff16 = (uint32_t)((wm * 32 + (lane & 7) + ((lane >> 3) & 1) * 8) * ASTRIDE)
                          + ((lane >> 4) & 1) * 16;
    const uint32_t boff16 = (uint32_t)((wn * 32 + (lane & 7) + ((lane >> 4) & 1) * 8) * BSTRIDE)
                          + ((lane >> 3) & 1) * 16;
    // int8 ldmatrix per-lane offsets:
    // A: submatrices (rows0-7,+0)(rows8-15,+0)(rows0-7,+16)(rows8-15,+16)
    const uint32_t a8lds = (uint32_t)((wm * 32 + (lane & 7) + ((lane >> 3) & 1) * 8) * ASTRIDE)
                         + ((lane >> 4) & 1) * 16;
    // B: submatrices (n0-7,+0)(n0-7,+16)(n8-15,+0)(n8-15,+16)
    const uint32_t b8lds = (uint32_t)((wn * 32 + (lane & 7) + ((lane >> 4) & 1) * 8) * BSTRIDE)
                         + ((lane >> 3) & 1) * 16;

    float accf[2][4][4];
    int   acci[2][4][4];

#pragma unroll 1
    for (int gs = 0; gs < GSLICES; ++gs) {
        const int chunk = gs >> 3;
        const int s = gs & 7;
        if (s == 0) {
#pragma unroll
            for (int mf = 0; mf < 2; ++mf)
#pragma unroll
                for (int nf = 0; nf < 4; ++nf)
#pragma unroll
                    for (int c = 0; c < 4; ++c) { accf[mf][nf][c] = 0.f; acci[mf][nf][c] = 0; }
        }

        const uint32_t bar = MB + (uint32_t)(gs & 1) * 8;
        MBAR_WAIT(bar, (gs >> 1) & 1);
        const uint32_t bbuf = Bb + (uint32_t)(gs & 1) * BSLICE;

        if (s < 4) {
            // ---- fp16 slice: K=64 of yh*Wh ----
            const uint32_t bbase = bbuf + boff16;
            const uint32_t abase = A16b + aoff16 + (uint32_t)s * 128u;
#pragma unroll
            for (int t4 = 0; t4 < 4; ++t4) {
                uint32_t br[2][4], a[2][4];
#pragma unroll
                for (int nb = 0; nb < 2; ++nb)
                    LDSM4(br[nb], bbase + (uint32_t)nb * (16u * BSTRIDE) + (uint32_t)t4 * 32u);
#pragma unroll
                for (int mf = 0; mf < 2; ++mf)
                    LDSM4(a[mf], abase + (uint32_t)mf * (16u * ASTRIDE) + (uint32_t)t4 * 32u);
#pragma unroll
                for (int mf = 0; mf < 2; ++mf)
#pragma unroll
                    for (int nf = 0; nf < 4; ++nf)
                        MMA16816(accf[mf][nf], a[mf], br[nf >> 1][(nf & 1) * 2],
                                 br[nf >> 1][(nf & 1) * 2 + 1]);
            }
        } else {
            // ---- int8 slice: K=128 of [ql|qy]*[QWh;QWl], ldmatrix loads ----
            const uint32_t kw = (uint32_t)(s - 4) * 128u;
#pragma unroll
            for (int t4 = 0; t4 < 4; ++t4) {
                const uint32_t kt = (uint32_t)t4 * 32u;   // k window inside B slice
                uint32_t bF[2][4], aF[2][4];
#pragma unroll
                for (int nfp = 0; nfp < 2; ++nfp)
                    LDSM4(bF[nfp], bbuf + b8lds + (uint32_t)nfp * (16u * BSTRIDE) + kt);
#pragma unroll
                for (int mf = 0; mf < 2; ++mf)
                    LDSM4(aF[mf], A8b + a8lds + (uint32_t)mf * (16u * ASTRIDE) + kw + kt);
#pragma unroll
                for (int mf = 0; mf < 2; ++mf)
#pragma unroll
                    for (int nf = 0; nf < 4; ++nf)
                        IMMA16832(acci[mf][nf], aF[mf], bF[nf >> 1][(nf & 1) * 2],
                                  bF[nf >> 1][(nf & 1) * 2 + 1]);
            }
        }

        __syncthreads();
        if (tid == 0 && gs + 2 < GSLICES) {
            MBAR_EXPECT(bar, BSLICE);
            bulk_g2s(Bb + (uint32_t)(gs & 1) * BSLICE,
                     d_B + (size_t)(gs + 2) * BSLICE, BSLICE, bar);
        }

        // chunk epilogue: psi = accf + S*acci; p; fold signs into zacc
        if (s == 7) {
#pragma unroll
            for (int mf = 0; mf < 2; ++mf)
#pragma unroll
                for (int rh = 0; rh < 2; ++rh) {
                    const int row = wm * 32 + mf * 16 + (lane >> 2) + rh * 8;
                    float cz[8];
#pragma unroll
                    for (int i = 0; i < 8; ++i) cz[i] = 0.f;
#pragma unroll
                    for (int nf = 0; nf < 4; ++nf) {
                        const float x0 = accf[mf][nf][rh * 2]     + S_CORR * (float)acci[mf][nf][rh * 2];
                        const float x1 = accf[mf][nf][rh * 2 + 1] + S_CORR * (float)acci[mf][nf][rh * 2 + 1];
                        const float p = x0 * x0 + x1 * x1;
                        const int k = chunk * 64 + wn * 16 + nf * 4 + (lane & 3);
#pragma unroll
                        for (int i = 0; i < 8; ++i)
                            cz[i] += ((k >> (7 - i)) & 1) ? -p : p;
                    }
#pragma unroll
                    for (int i = 0; i < 8; ++i) {
                        cz[i] += __shfl_down_sync(0xffffffffu, cz[i], 1);
                        cz[i] += __shfl_down_sync(0xffffffffu, cz[i], 2);
                    }
                    if ((lane & 3) == 0) {
                        float* zp = zacc + ((size_t)wn * 64 + row) * 8;
#pragma unroll
                        for (int i = 0; i < 8; ++i) zp[i] += cz[i];
                    }
                }
        }
    }

    // final z reduction across the 4 N-warp planes
    __syncthreads();
    {
        const int r = tid >> 2, o = tid & 3;   // row 0..63, comp pair 0..3
        float2 sum = make_float2(0.f, 0.f);
#pragma unroll
        for (int wnn = 0; wnn < 4; ++wnn) {
            const float* zp = zacc + ((size_t)wnn * 64 + r) * 8 + o * 2;
            sum.x += zp[0];
            sum.y += zp[1];
        }
        *(float2*)(out + (size_t)(b0 + r) * 8 + o * 2) = sum;
    }
}

// ============================================================
extern "C" void kernel_launch(void* const* d_in, const int* in_sizes, int n_in,
                              void* d_out, int out_size) {
    const float* inputs  = (const float*)d_in[0];  // (65536, 8) float32
    const float* weights = (const float*)d_in[1];  // (6, 8, 3) float32
    float* out = (float*)d_out;                    // (65536, 8) float32

    const int B = in_sizes[0] / NQ;

    static int configured = 0;
    if (!configured) {
        cudaFuncSetAttribute(sim_kernel, cudaFuncAttributeMaxDynamicSharedMemorySize, SMEM_TOTAL);
        configured = 1;
    }

    build_U_kernel<<<DIM, 128>>>(weights);
    sim_kernel<<<B / MT, 256, SMEM_TOTAL>>>(inputs, out);
}